// round 14
// baseline (speedup 1.0000x reference)
#include <cuda_runtime.h>
#include <cstdint>

// Neighborlist brute N^2, upper-triangular pairs, PBC minimum image.
// N=6000 -> P = 17,997,000 pairs. Output float32, concatenated tuple:
//   [0,    P)   : masked i indices (-1 if out of cutoff)
//   [P,   2P)   : masked j indices
//   [2P,  3P)   : d_ij (0 if out of cutoff)
//   [3P,  6P)   : r_ij row-major [P,3] (0 if out of cutoff)
//
// Warp-coalesced mapping + smem staging. Warp w owns pairs [128w, 128w+128);
// lane handles pairs 128w + 32u + lane. The warp's 384 j-position floats are
// preloaded coalesced into smem (stride-3 LDS reads, conflict-free), and the
// warp's 1536-byte contiguous r_ij block is staged in smem and written out
// as 3 coalesced STG.128 per lane.

#define N_PART   6000
#define P_TOTAL  17997000      // N*(N-1)/2, fits int32
#define CUTOFF_F 0.5f
#define WARPS_TOTAL ((P_TOTAL + 127) / 128)   // 140,602
#define WARPS_PER_BLOCK 8

__device__ __forceinline__ int row_off(int i) {
    // offset of first pair of row i in triu(k=1) ordering (fits int32)
    return i * (2 * N_PART - i - 1) / 2;
}

// Bitwise-identical to: m = fmodf(r + halfL, L); if (m != 0 && m < 0) m += L;
// return m - halfL;  -- valid since positions in [0, L) => t = r+halfL in (-L/2, 3L/2):
//   t >= L : fmod = t - L (Sterbenz-exact true remainder)
//   0<=t<L : fmod = t
//   t <  0 : fmod = t exactly, then +L rounds identically to the reference path
__device__ __forceinline__ float floormod_wrap(float r, float L, float halfL) {
    float t = __fadd_rn(r, halfL);
    float m = t;
    m = (t >= L)   ? __fadd_rn(t, -L) : m;
    m = (t < 0.0f) ? __fadd_rn(t,  L) : m;
    return __fadd_rn(m, -halfL);
}

// invert pair index p -> i (row), via f32 sqrt estimate + bounded fixup
__device__ __forceinline__ int invert_row(int p) {
    const float twoNm1 = 2.0f * N_PART - 1.0f;
    int disc_i = (2 * N_PART - 1) * (2 * N_PART - 1) - 8 * p;   // exact int32
    float s = __fsqrt_rn(__int2float_rn(disc_i));
    int i = (int)((twoNm1 - s) * 0.5f);
    if (i > N_PART - 2) i = N_PART - 2;
    if (i < 0) i = 0;
    while (i < N_PART - 2 && row_off(i + 1) <= p) ++i;
    while (i > 0 && row_off(i) > p) --i;
    return i;
}

// Exact XLA math sequence. Returns d and wrapped r via refs; mask applied by caller.
__device__ __forceinline__ bool pair_math(
    float xi, float yi, float zi, float xj, float yj, float zj,
    int periodic, float Lx, float Ly, float Lz, float hx, float hy, float hz,
    float& rx, float& ry, float& rz, float& d)
{
    rx = __fadd_rn(xi, -xj);
    ry = __fadd_rn(yi, -yj);
    rz = __fadd_rn(zi, -zj);
    if (periodic) {
        rx = floormod_wrap(rx, Lx, hx);
        ry = floormod_wrap(ry, Ly, hy);
        rz = floormod_wrap(rz, Lz, hz);
    }
    // XLA order: rounded squares, then ((x2 + y2) + z2). No FMA contraction.
    float x2 = __fmul_rn(rx, rx);
    float y2 = __fmul_rn(ry, ry);
    float z2 = __fmul_rn(rz, rz);
    float d2 = __fadd_rn(__fadd_rn(x2, y2), z2);
    d = __fsqrt_rn(d2);
    return (d <= CUTOFF_F);
}

__global__ __launch_bounds__(256)
void neighborlist_kernel(const float* __restrict__ pos,
                         const float* __restrict__ box,
                         const int* __restrict__ is_periodic,
                         float* __restrict__ out)
{
    __shared__ float s_j[WARPS_PER_BLOCK][384];   // warp's 128 j-positions (xyz)
    __shared__ float s_r[WARPS_PER_BLOCK][384];   // warp's 128 r_ij vectors

    int wip  = threadIdx.x >> 5;
    int lane = threadIdx.x & 31;
    int warp_g = blockIdx.x * WARPS_PER_BLOCK + wip;
    if (warp_g >= WARPS_TOTAL) return;
    int base = warp_g * 128;        // first pair of this warp

    const int periodic = __ldg(is_periodic);
    const float Lx = __ldg(&box[0]);
    const float Ly = __ldg(&box[4]);
    const float Lz = __ldg(&box[8]);
    const float hx = __fmul_rn(Lx, 0.5f);
    const float hy = __fmul_rn(Ly, 0.5f);
    const float hz = __fmul_rn(Lz, 0.5f);

    // warp-uniform inversion of the warp's first pair
    int i0 = invert_row(base);
    int j0 = i0 + 1 + (base - row_off(i0));

    if (j0 + 127 <= N_PART - 1 && base + 127 < P_TOTAL) {
        // ---- fast path (~97% of warps): all 128 pairs in row i0 ----

        // coalesced preload of pos[j0 .. j0+127] (384 consecutive floats)
        const float* src = pos + 3 * j0;
        #pragma unroll
        for (int m = 0; m < 12; ++m)
            s_j[wip][lane + 32 * m] = __ldg(&src[lane + 32 * m]);
        __syncwarp();

        float xi = __ldg(&pos[3 * i0 + 0]);   // warp-uniform (1 wf each)
        float yi = __ldg(&pos[3 * i0 + 1]);
        float zi = __ldg(&pos[3 * i0 + 2]);

        #pragma unroll
        for (int u = 0; u < 4; ++u) {
            int q = u * 32 + lane;            // pair-in-warp
            int p = base + q;
            float xj = s_j[wip][3 * q + 0];   // stride-3 LDS: conflict-free
            float yj = s_j[wip][3 * q + 1];
            float zj = s_j[wip][3 * q + 2];

            float rx, ry, rz, d;
            bool in_cut = pair_math(xi, yi, zi, xj, yj, zj,
                                    periodic, Lx, Ly, Lz, hx, hy, hz,
                                    rx, ry, rz, d);

            out[p]               = in_cut ? (float)i0       : -1.0f;  // coalesced
            out[P_TOTAL + p]     = in_cut ? (float)(j0 + q) : -1.0f;
            out[2 * P_TOTAL + p] = in_cut ? d : 0.0f;

            s_r[wip][3 * q + 0] = in_cut ? rx : 0.0f;   // stride-3 STS: conflict-free
            s_r[wip][3 * q + 1] = in_cut ? ry : 0.0f;
            s_r[wip][3 * q + 2] = in_cut ? rz : 0.0f;
        }
        __syncwarp();

        // contiguous 1536-byte r_ij block, written coalesced as float4
        // 3*P_TOTAL % 4 == 0 and 3*base = 384*warp_g % 4 == 0 -> aligned
        const float4* s4 = (const float4*)s_r[wip];
        float4* dst = (float4*)(out + 3 * P_TOTAL + 3 * base);
        #pragma unroll
        for (int m = 0; m < 3; ++m)
            dst[lane + 32 * m] = s4[lane + 32 * m];
    } else {
        // ---- slow path: row boundary inside warp, or tail ----
        #pragma unroll
        for (int u = 0; u < 4; ++u) {
            int p = base + u * 32 + lane;
            if (p >= P_TOTAL) continue;
            int i = invert_row(p);
            int j = i + 1 + (p - row_off(i));
            float xi = __ldg(&pos[3 * i + 0]);
            float yi = __ldg(&pos[3 * i + 1]);
            float zi = __ldg(&pos[3 * i + 2]);
            float xj = __ldg(&pos[3 * j + 0]);
            float yj = __ldg(&pos[3 * j + 1]);
            float zj = __ldg(&pos[3 * j + 2]);

            float rx, ry, rz, d;
            bool in_cut = pair_math(xi, yi, zi, xj, yj, zj,
                                    periodic, Lx, Ly, Lz, hx, hy, hz,
                                    rx, ry, rz, d);

            out[p]               = in_cut ? (float)i : -1.0f;
            out[P_TOTAL + p]     = in_cut ? (float)j : -1.0f;
            out[2 * P_TOTAL + p] = in_cut ? d : 0.0f;
            int rbase = 3 * P_TOTAL + 3 * p;
            out[rbase + 0] = in_cut ? rx : 0.0f;
            out[rbase + 1] = in_cut ? ry : 0.0f;
            out[rbase + 2] = in_cut ? rz : 0.0f;
        }
    }
}

extern "C" void kernel_launch(void* const* d_in, const int* in_sizes, int n_in,
                              void* d_out, int out_size)
{
    const float* pos = (const float*)d_in[0];       // [6000, 3] float32
    const float* box = (const float*)d_in[1];       // [3, 3] float32
    const int*   per = (const int*)d_in[2];         // scalar int32

    float* out = (float*)d_out;

    const int threads = 256;  // 8 warps/block
    const int blocks = (WARPS_TOTAL + WARPS_PER_BLOCK - 1) / WARPS_PER_BLOCK;  // 17,576
    neighborlist_kernel<<<blocks, threads>>>(pos, box, per, out);
}